// round 15
// baseline (speedup 1.0000x reference)
#include <cuda_runtime.h>

#define NQ    14
#define DEPTH 6
#define TPB   1024     // 10 thread bits
#define AMPS  16       // 4 local bits
#define SSEG  580      // ull per warp segment (injective + conflict-free slot design)
#define BUFN  (32*SSEG)
#define SGNM  0x8000000080000000ULL

typedef unsigned long long ull;

// ---------- packed f32x2 helpers ----------
__device__ __forceinline__ ull pack2(float x, float y){
    ull r; asm("mov.b64 %0,{%1,%2};" : "=l"(r) : "f"(x), "f"(y)); return r;
}
__device__ __forceinline__ void unpack2(ull v, float& x, float& y){
    asm("mov.b64 {%0,%1},%2;" : "=f"(x), "=f"(y) : "l"(v));
}
__device__ __forceinline__ ull f2mul(ull a, ull b){
    ull d; asm("mul.rn.f32x2 %0,%1,%2;" : "=l"(d) : "l"(a), "l"(b)); return d;
}
__device__ __forceinline__ ull f2fma(ull a, ull b, ull c){
    ull d; asm("fma.rn.f32x2 %0,%1,%2,%3;" : "=l"(d) : "l"(a), "l"(b), "l"(c)); return d;
}
__device__ __forceinline__ ull cmul(ull av, float ur, float ui){
    float xx, yy; unpack2(av, xx, yy);
    ull t1 = f2mul(pack2(ur, ur), av);
    return f2fma(pack2(-ui, ui), pack2(yy, xx), t1);
}

// Paeth 3-shear: lo -= T*hi ; hi += S*lo ; lo -= T*hi
__device__ __forceinline__ void pairG(ull* a, int lo, int hi, ull nT, ull S){
    ull a0 = a[lo], a1 = a[hi];
    a0 = f2fma(nT, a1, a0);
    a1 = f2fma(S,  a0, a1);
    a0 = f2fma(nT, a1, a0);
    a[lo] = a0; a[hi] = a1;
}

// Plain RY on local bit K (8 pairs, 16 amps)
template<int K>
__device__ __forceinline__ void gate8(ull* a, ull nT, ull S){
#pragma unroll
    for (int m = 0; m < 8; m++){
        int lo = ((m >> K) << (K + 1)) | (m & ((1 << K) - 1));
        pairG(a, lo, lo | (1 << K), nT, S);
    }
}

// Merged gate M = RY(b)*diag(1,r)*RY(a): when r=-1 flip hi sign then rotate by (b-a);
// when r=+1 rotate by (a+b). r parity from local mask NBM + thread part tp.
template<int K, int NBM>
__device__ __forceinline__ void mgate8(ull* a, ull sT, ull sS, ull dT, ull dS, int tp){
    ull cT0 = tp ? dT : sT, cS0 = tp ? dS : sS;
    ull cT1 = tp ? sT : dT, cS1 = tp ? sS : dS;
    ull F0  = tp ? SGNM : 0ULL;
    ull F1  = F0 ^ SGNM;
#pragma unroll
    for (int m = 0; m < 8; m++){
        int lo = ((m >> K) << (K + 1)) | (m & ((1 << K) - 1));
        int hi = lo | (1 << K);
        int lp = __popc(lo & NBM) & 1;
        if (lp){ a[hi] ^= F1; pairG(a, lo, hi, cT1, cS1); }
        else   { a[hi] ^= F0; pairG(a, lo, hi, cT0, cS0); }
    }
}

__device__ __forceinline__ void applyCZ(ull* amp, unsigned mask){
#pragma unroll
    for (int l = 0; l < AMPS; l++)
        if ((mask >> l) & 1u) amp[l] ^= SGNM;
}

// ---------- layouts ----------
// evens e_k = phys 2k, odds o_k = phys 2k+1 (k=0..6)
// E1: local(e0..e3)      lane(e4,e5,e6,o5,o6)  warp(o0..o4)
// E2: local(e4,e5,e6,o6) lane(e0..e3,o5)       warp(o0..o4)
// O1: local(o0..o3)      lane(o4,o5,o6,e5,e6)  warp(e0..e4)
// O2: local(o4,o5,o6,e6) lane(o0..o3,e5)       warp(e0..e4)
//
// Intra slot (per warp, x=resident parity, y=other):
//   sig = c(x0..x3) + 17*(x4+2x5+4x6) + 136*y5 + 280*y6
//   ranges [0,134]+[136,270]+[280,414]+[416,550] -> injective, max 550 < SSEG
// Cross slot (global):
//   Sig = SSEG*(y0..y4) + y4 + 148*y5 + 296*y6 + c(x0..x3) + 17*(x4+2x5+4x6)
//   in-seg ranges [0,135]/[148,283]/[296,431]/[444,579] -> injective, 579 < SSEG
//   lane-stride residues mod 16 distinct per LDS.64 phase -> conflict-free

__device__ __forceinline__ void intraX(ull* buf, ull* amp, int w, int L){
    ull* tile = buf + w * SSEG;
    ull* sp = tile + 17 * (L & 7) + 136 * ((L >> 3) & 1) + 280 * ((L >> 4) & 1);
    __syncwarp();
#pragma unroll
    for (int l = 0; l < AMPS; l++) sp[l] = amp[l];
    __syncwarp();
    ull* ldp = tile + (L & 15) + 136 * ((L >> 4) & 1);
#pragma unroll
    for (int l = 0; l < AMPS; l++) amp[l] = ldp[17 * (l & 7) + 280 * (l >> 3)];
}

__device__ __forceinline__ void crossStore(ull* buf, ull* amp, int w, int L){
    __syncwarp();   // own-tile cross-lane reads done
    ull* sp = buf + w * SSEG + (w >> 4) + 148 * ((L >> 4) & 1) + (L & 15);
#pragma unroll
    for (int l = 0; l < AMPS; l++) sp[17 * (l & 7) + 296 * (l >> 3)] = amp[l];
}

__device__ __forceinline__ void crossLoad(ull* buf, ull* amp, int w, int L){
    const int t0 = L & 1, t1 = (L >> 1) & 1, t2 = (L >> 2) & 1, t3 = (L >> 3) & 1, t4 = (L >> 4) & 1;
    ull* ldp = buf + t0 * (16 * SSEG + 1) + 148 * t1 + 296 * t2 + 34 * t3 + 68 * t4
                   + (w & 15) + 17 * (w >> 4);
#pragma unroll
    for (int l = 0; l < AMPS; l++) amp[l] = ldp[l * SSEG];
}

// ---------- smem float-region offsets ----------
#define TABN    84
#define OFF_U0R 0
#define OFF_U0I 14
#define OFF_U1R 28
#define OFF_U1I 42
#define OFF_RED 56                     // 32 warps x 14
#define OFF_ZF  (56 + 32*NQ)           // 504
#define N_FLOATS (OFF_ZF + NQ)         // 518
#define SMEM_BYTES ((unsigned)((BUFN + 4*TABN) * 8u) + (N_FLOATS * 4u))

__global__ void __launch_bounds__(TPB, 1)
qc_kernel(const float* __restrict__ x,
          const float* __restrict__ theta,
          const float* __restrict__ head_w,
          const float* __restrict__ head_b,
          float* __restrict__ out)
{
    extern __shared__ ull sh[];
    ull*   buf  = sh;
    ull*   sumT = sh + BUFN;
    ull*   sumS = sumT + TABN;
    ull*   difT = sumS + TABN;
    ull*   difS = difT + TABN;
    float* fex  = (float*)(difS + TABN);
    float* u0r  = fex + OFF_U0R;
    float* u0i  = fex + OFF_U0I;
    float* u1r  = fex + OFF_U1R;
    float* u1i  = fex + OFF_U1I;
    float* red  = fex + OFF_RED;
    float* zf   = fex + OFF_ZF;

    const int t = threadIdx.x;
    const int b = blockIdx.x;
    const int L = t & 31, w = t >> 5;

    // ----- per-qubit init vectors: u_p = RY(theta_L0)*RX(x)|0>, phys p, q=13-p -----
    if (t < NQ){
        int p = t, q = 13 - p;
        float h  = 0.5f * x[b * NQ + q];
        float c  = cosf(h), s = sinf(h);
        float A0 = 0.5f * theta[q];
        float ca = cosf(A0), sa = sinf(A0);
        u0r[p] = ca * c;  u0i[p] = sa * s;
        u1r[p] = sa * c;  u1i[p] = -ca * s;
    }
    // ----- stage coefficient tables (idx = s*14 + p) -----
    if (t < TABN){
        int s = t / NQ, p = t % NQ, q = 13 - p;
        float sum, dif;
        if (s == 0){ sum = theta[NQ + q];        dif = 0.f; }
        else if (s == 5){ sum = theta[5*NQ + q]; dif = 0.f; }
        else { float a = theta[s*NQ + q], bb = theta[(s+1)*NQ + q]; sum = a + bb; dif = bb - a; }
        float st = -tanf(0.25f * sum), ss = sinf(0.5f * sum);
        float dt = -tanf(0.25f * dif), ds = sinf(0.5f * dif);
        sumT[t] = pack2(st, st); sumS[t] = pack2(ss, ss);
        difT[t] = pack2(dt, dt); difS[t] = pack2(ds, ds);
    }

    // ----- thread bits -----
    const int b0 = t & 1, b1 = (t >> 1) & 1, b2 = (t >> 2) & 1, b3 = (t >> 3) & 1, b4 = (t >> 4) & 1;
    const int b5 = (t >> 5) & 1, b6 = (t >> 6) & 1, b7 = (t >> 7) & 1, b8 = (t >> 8) & 1, b9 = (t >> 9) & 1;

    // ----- CZ parity masks (layouts E1 and O2) -----
    unsigned czE1 = 0, czO2 = 0;
#pragma unroll
    for (int l = 0; l < AMPS; l++){
        int l0 = l & 1, l1 = (l >> 1) & 1, l2 = (l >> 2) & 1, l3 = (l >> 3) & 1;
        int iE = l0*1 + l1*4 + l2*16 + l3*64
               + b0*256 + b1*1024 + b2*4096 + b3*2048 + b4*8192
               + b5*2 + b6*8 + b7*32 + b8*128 + b9*512;
        int iO = l0*512 + l1*2048 + l2*8192 + l3*4096
               + b0*2 + b1*8 + b2*32 + b3*128 + b4*1024
               + b5*1 + b6*4 + b7*16 + b8*64 + b9*256;
        czE1 |= (unsigned)(__popc(iE & (iE >> 1)) & 1) << l;
        czO2 |= (unsigned)(__popc(iO & (iO >> 1)) & 1) << l;
    }
    __syncthreads();

    // ----- initial product state in E1 (layer 0 folded) -----
    ull amp[AMPS];
    {
        const int physT[10] = {8,10,12,11,13,1,3,5,7,9};
        float rre = 1.f, rim = 0.f;
#pragma unroll
        for (int j = 0; j < 10; j++){
            int p = physT[j], bb = (t >> j) & 1;
            float ur = bb ? u1r[p] : u0r[p];
            float ui = bb ? u1i[p] : u0i[p];
            float nr = rre * ur - rim * ui;
            float ni = rre * ui + rim * ur;
            rre = nr; rim = ni;
        }
        amp[0] = pack2(rre, rim);
#pragma unroll
        for (int j = 0; j < 4; j++){
            int p = 2 * j;
            float a0r = u0r[p], a0i = u0i[p], a1r = u1r[p], a1i = u1i[p];
#pragma unroll
            for (int l = 0; l < (1 << j); l++){
                amp[l | (1 << j)] = cmul(amp[l], a1r, a1i);
                amp[l]            = cmul(amp[l], a0r, a0i);
            }
        }
    }
    applyCZ(amp, czE1);   // CZ0

#define PG(K, s, p) do { ull T_=sumT[(s)*14+(p)], S_=sumS[(s)*14+(p)]; gate8<K>(amp, T_, S_); } while (0)
#define MG(K, NBM, s, p, TP) do { int tp_=(TP); \
        ull sT_=sumT[(s)*14+(p)], sS_=sumS[(s)*14+(p)]; \
        ull dT_=difT[(s)*14+(p)], dS_=difS[(s)*14+(p)]; \
        mgate8<K, NBM>(amp, sT_, sS_, dT_, dS_, tp_); } while (0)

    // ===== S1: plain L1 even (E1 -> E2 -> cross) =====
    PG(0,0,0); PG(1,0,2); PG(2,0,4); PG(3,0,6);
    intraX(buf, amp, w, L);
    PG(0,0,8); PG(1,0,10); PG(2,0,12);
    crossStore(buf, amp, w, L); __syncthreads(); crossLoad(buf, amp, w, L);
    // ===== S2: merged L1+CZ1+L2 odd (O1 -> O2 -> cross) =====
    MG(0,0,1,1, b5^b6); MG(1,0,1,3, b6^b7); MG(2,0,1,5, b7^b8); MG(3,0,1,7, b8^b9);
    __syncthreads();
    intraX(buf, amp, w, L);
    MG(0,0,1,9, b9^b4); MG(1,8,1,11, b4); MG(2,8,1,13, 0);
    crossStore(buf, amp, w, L); __syncthreads(); crossLoad(buf, amp, w, L);
    // ===== S3: merged L2+CZ2+L3 even =====
    MG(0,0,2,0, b5); MG(1,0,2,2, b5^b6); MG(2,0,2,4, b6^b7); MG(3,0,2,6, b7^b8);
    __syncthreads();
    intraX(buf, amp, w, L);
    MG(0,0,2,8, b8^b9); MG(1,0,2,10, b9^b4); MG(2,8,2,12, b4);
    crossStore(buf, amp, w, L); __syncthreads(); crossLoad(buf, amp, w, L);
    // ===== S4: merged L3+CZ3+L4 odd =====
    MG(0,0,3,1, b5^b6); MG(1,0,3,3, b6^b7); MG(2,0,3,5, b7^b8); MG(3,0,3,7, b8^b9);
    __syncthreads();
    intraX(buf, amp, w, L);
    MG(0,0,3,9, b9^b4); MG(1,8,3,11, b4); MG(2,8,3,13, 0);
    crossStore(buf, amp, w, L); __syncthreads(); crossLoad(buf, amp, w, L);
    // ===== S5: merged L4+CZ4+L5 even =====
    MG(0,0,4,0, b5); MG(1,0,4,2, b5^b6); MG(2,0,4,4, b6^b7); MG(3,0,4,6, b7^b8);
    __syncthreads();
    intraX(buf, amp, w, L);
    MG(0,0,4,8, b8^b9); MG(1,0,4,10, b9^b4); MG(2,8,4,12, b4);
    crossStore(buf, amp, w, L); __syncthreads(); crossLoad(buf, amp, w, L);
    // ===== S6: plain L5 odd =====
    PG(0,5,1); PG(1,5,3); PG(2,5,5); PG(3,5,7);
    __syncthreads();
    intraX(buf, amp, w, L);
    PG(0,5,9); PG(1,5,11); PG(2,5,13);
    applyCZ(amp, czO2);   // CZ5

#undef PG
#undef MG

    // ----- epilogue (layout O2): probs -> per-phys Z -> head GEMV -----
    float S = 0.0f;
    float zl0 = 0.f, zl1 = 0.f, zl2 = 0.f, zl3 = 0.f;
#pragma unroll
    for (int l = 0; l < AMPS; l++){
        float re, im; unpack2(amp[l], re, im);
        float pr = fmaf(re, re, im * im);
        S += pr;
        zl0 += (l & 1) ? -pr : pr;
        zl1 += (l & 2) ? -pr : pr;
        zl2 += (l & 4) ? -pr : pr;
        zl3 += (l & 8) ? -pr : pr;
    }
    float z[NQ];
    z[9]  = zl0; z[11] = zl1; z[13] = zl2; z[12] = zl3;
    z[1]  = b0 ? -S : S;  z[3]  = b1 ? -S : S;  z[5] = b2 ? -S : S;  z[7] = b3 ? -S : S;
    z[10] = b4 ? -S : S;  z[0]  = b5 ? -S : S;  z[2] = b6 ? -S : S;  z[4] = b7 ? -S : S;
    z[6]  = b8 ? -S : S;  z[8]  = b9 ? -S : S;

#pragma unroll
    for (int off = 16; off; off >>= 1)
#pragma unroll
        for (int p = 0; p < NQ; p++)
            z[p] += __shfl_xor_sync(0xFFFFFFFFu, z[p], off);

    if (L == 0){
#pragma unroll
        for (int p = 0; p < NQ; p++) red[w * NQ + p] = z[p];
    }
    __syncthreads();
    if (t < NQ){
        float a = 0.0f;
#pragma unroll
        for (int ww = 0; ww < TPB / 32; ww++) a += red[ww * NQ + t];
        zf[t] = a;
    }
    __syncthreads();
    if (t < 2){
        float a = head_b[t];
#pragma unroll
        for (int p = 0; p < NQ; p++) a = fmaf(head_w[t * NQ + p], zf[p], a);
        out[b * 2 + t] = a;
    }
}

extern "C" void kernel_launch(void* const* d_in, const int* in_sizes, int n_in,
                              void* d_out, int out_size)
{
    const float* x      = (const float*)d_in[0];
    const float* theta  = (const float*)d_in[1];
    const float* head_w = (const float*)d_in[2];
    const float* head_b = (const float*)d_in[3];
    float* out = (float*)d_out;

    cudaFuncSetAttribute(qc_kernel, cudaFuncAttributeMaxDynamicSharedMemorySize, SMEM_BYTES);
    qc_kernel<<<512, TPB, SMEM_BYTES>>>(x, theta, head_w, head_b, out);
}